// round 10
// baseline (speedup 1.0000x reference)
#include <cuda_runtime.h>

#define NT 256
#define L_IN 4096
#define DZV 30
#define CV 10
#define NPG 15
#define B_TOT 512

typedef unsigned long long u64;

__constant__ float cWh[DZV*80];   // [d][c][j]
__constant__ float cZ[DZV];

// per-net block of 408 u64, all weights pre-duplicated (w,w):
// [0..96)    conv1: ch*12 + k*4 + oc      (ch<8, k<3, oc<4)
// [96..192)  conv2: 96 + ch*24 + k*8 + oc (ch<4, k<3, oc<8)
// [192..384) conv3: 192 + ch*24 + k*8 + oc (ch<8)
// [384..388) b1d, [388..396) b2d, [396..404) b3d, pad 408
__device__ u64 g_wdup[DZV*408];

__device__ __forceinline__ u64 f2u(float a, float b) {
    union { float2 f; u64 u; } c; c.f = make_float2(a, b); return c.u;
}
__device__ __forceinline__ float2 u2f(u64 v) {
    union { float2 f; u64 u; } c; c.u = v; return c.f;
}
__device__ __forceinline__ u64 ffma2(u64 a, u64 b, u64 c) {
    u64 d; asm("fma.rn.f32x2 %0, %1, %2, %3;" : "=l"(d) : "l"(a), "l"(b), "l"(c)); return d;
}
__device__ __forceinline__ void tap4(u64* acc, u64 t, ulonglong2 wa, ulonglong2 wb) {
    acc[0] = ffma2(wa.x, t, acc[0]);
    acc[1] = ffma2(wa.y, t, acc[1]);
    acc[2] = ffma2(wb.x, t, acc[2]);
    acc[3] = ffma2(wb.y, t, acc[3]);
}
__device__ __forceinline__ void tap8(u64* acc, u64 t, const ulonglong2* w4) {
    acc[0] = ffma2(w4[0].x, t, acc[0]);
    acc[1] = ffma2(w4[0].y, t, acc[1]);
    acc[2] = ffma2(w4[1].x, t, acc[2]);
    acc[3] = ffma2(w4[1].y, t, acc[3]);
    acc[4] = ffma2(w4[2].x, t, acc[4]);
    acc[5] = ffma2(w4[2].y, t, acc[5]);
    acc[6] = ffma2(w4[3].x, t, acc[6]);
    acc[7] = ffma2(w4[3].y, t, acc[7]);
}

__global__ void prep_kernel(const float* __restrict__ W1, const float* __restrict__ b1,
                            const float* __restrict__ W2, const float* __restrict__ b2,
                            const float* __restrict__ W3, const float* __restrict__ b3,
                            const float* __restrict__ z,  const float* __restrict__ bh,
                            float* __restrict__ out) {
    int i = blockIdx.x * blockDim.x + threadIdx.x;
    if (i < DZV*404) {
        int n = i / 404, r = i % 404;
        float v;
        if (r < 96) {
            int ch = r / 12, k = (r % 12) / 4, oc = r & 3;
            v = W1[n*96 + oc*24 + ch*3 + k];
        } else if (r < 192) {
            int t = r - 96, ch = t / 24, k = (t % 24) / 8, oc = t & 7;
            v = W2[n*96 + oc*12 + ch*3 + k];
        } else if (r < 384) {
            int t = r - 192, ch = t / 24, k = (t % 24) / 8, oc = t & 7;
            v = W3[n*192 + oc*24 + ch*3 + k];
        } else if (r < 388) v = b1[n*4 + (r-384)];
        else if (r < 396)   v = b2[n*8 + (r-388)];
        else                v = b3[n*8 + (r-396)];
        g_wdup[n*408 + r] = f2u(v, v);
    }
    if (i < B_TOT*CV) {
        int c = i % CV;
        float s = 0.f;
        #pragma unroll
        for (int d = 0; d < DZV; d++) s = fmaf(z[d], bh[d*CV + c], s);
        out[i] = s;
    }
}

// ---- smem float offsets ----
#define XE_BASE 0           // [8][2056]
#define XO_BASE 16448       // [8][2056]
#define RED_OFF 32896       // [8 warps][8]
#define HAL_OFF 32960       // 8 warps x 8 u64 halo posts (128 floats)
#define WS_OFF  33088       // 2 x 816 floats (ping-pong weight buffers, 16B aligned)
#define SMEM_FLOATS 34720   // 138880 B

__global__ __launch_bounds__(NT, 1)
void ensemble_kernel(const int* __restrict__ ids,
                     const float* __restrict__ mask,
                     const float* __restrict__ embed,
                     float* __restrict__ out)
{
    extern __shared__ float sm[];
    float* red = sm + RED_OFF;
    u64*   hal = (u64*)(sm + HAL_OFF);

    const int tid  = threadIdx.x;
    const int lane = tid & 31;
    const int warp = tid >> 5;
    const int b    = blockIdx.x;
    const int g    = blockIdx.y;

    // ---- zero x pads (XE/XO indices 2048..2051, read by tail threads only) ----
    if (tid < 64) {
        int ch = tid >> 3, r = tid & 7;
        int base = (r < 4) ? XE_BASE : XO_BASE;
        sm[base + ch*2056 + 2048 + (r & 3)] = 0.f;
    }

    // ---- stage first net's weight block into buffer 0 ----
    if (tid < 204)
        ((float4*)(sm + WS_OFF))[tid] =
            __ldg((const float4*)(g_wdup + (size_t)(g*NPG)*408) + tid);

    // ---- gather masked embeddings, channel-major, even/odd deinterleaved ----
    #pragma unroll 1
    for (int i = tid; i < L_IN; i += NT) {
        int   id = __ldg(&ids[b*L_IN + i]);
        float m  = __ldg(&mask[b*L_IN + i]);
        float4 e0 = __ldg((const float4*)(embed + (size_t)id*8));
        float4 e1 = __ldg((const float4*)(embed + (size_t)id*8 + 4));
        int base = ((i & 1) ? XO_BASE : XE_BASE) + (i >> 1);
        sm[base + 0*2056] = e0.x*m; sm[base + 1*2056] = e0.y*m;
        sm[base + 2*2056] = e0.z*m; sm[base + 3*2056] = e0.w*m;
        sm[base + 4*2056] = e1.x*m; sm[base + 5*2056] = e1.y*m;
        sm[base + 6*2056] = e1.z*m; sm[base + 7*2056] = e1.w*m;
    }
    __syncthreads();

    float oacc = 0.f;   // warp0, lane<CV

    #pragma unroll 1
    for (int dn = 0; dn < NPG; dn++) {
        const int d = g*NPG + dn;
        const ulonglong2* WQ = (const ulonglong2*)(sm + WS_OFF + (dn & 1)*816);

        // ======== conv1: K3 S2, 8->4ch; thread owns r = 8t..8t+7 (+halo r=8t+8) ========
        u64   a1[4][4];   // [m][oc]: pair (h1[8t+2m], h1[8t+2m+1])
        float ax[4];      // halo scalar h1[8t+8]
        {
            ulonglong2 B0 = WQ[192], B1 = WQ[193];
            #pragma unroll
            for (int m = 0; m < 4; m++) {
                a1[m][0] = B0.x; a1[m][1] = B0.y;
                a1[m][2] = B1.x; a1[m][3] = B1.y;
            }
            ax[0] = u2f(B0.x).x; ax[1] = u2f(B0.y).x;
            ax[2] = u2f(B1.x).x; ax[3] = u2f(B1.y).x;
        }
        #pragma unroll 2
        for (int ch = 0; ch < 8; ch++) {
            ulonglong2 w00 = WQ[ch*6+0], w01 = WQ[ch*6+1];   // k0: oc01, oc23
            ulonglong2 w10 = WQ[ch*6+2], w11 = WQ[ch*6+3];   // k1
            ulonglong2 w20 = WQ[ch*6+4], w21 = WQ[ch*6+5];   // k2
            const float* XEr = sm + XE_BASE + ch*2056 + 8*tid;
            const float* XOr = sm + XO_BASE + ch*2056 + 8*tid;
            float4 A0 = *(const float4*)XEr;
            float4 A1 = *(const float4*)(XEr + 4);
            float2 A2 = *(const float2*)(XEr + 8);
            float4 C0 = *(const float4*)XOr;
            float4 C1 = *(const float4*)(XOr + 4);
            float  c8 = XOr[8];

            u64 tE[4] = { f2u(A0.x,A0.y), f2u(A0.z,A0.w), f2u(A1.x,A1.y), f2u(A1.z,A1.w) };
            u64 tO[4] = { f2u(C0.x,C0.y), f2u(C0.z,C0.w), f2u(C1.x,C1.y), f2u(C1.z,C1.w) };
            u64 tS[4] = { f2u(A0.y,A0.z), f2u(A0.w,A1.x), f2u(A1.y,A1.z), f2u(A1.w,A2.x) };
            #pragma unroll
            for (int m = 0; m < 4; m++) {
                tap4(a1[m], tE[m], w00, w01);
                tap4(a1[m], tO[m], w10, w11);
                tap4(a1[m], tS[m], w20, w21);
            }
            // halo scalar r=8t+8: taps (A2.x, c8, A2.y); scalar weights = low halves
            ax[0] = fmaf(u2f(w00.x).x, A2.x, ax[0]);
            ax[1] = fmaf(u2f(w00.y).x, A2.x, ax[1]);
            ax[2] = fmaf(u2f(w01.x).x, A2.x, ax[2]);
            ax[3] = fmaf(u2f(w01.y).x, A2.x, ax[3]);
            ax[0] = fmaf(u2f(w10.x).x, c8,   ax[0]);
            ax[1] = fmaf(u2f(w10.y).x, c8,   ax[1]);
            ax[2] = fmaf(u2f(w11.x).x, c8,   ax[2]);
            ax[3] = fmaf(u2f(w11.y).x, c8,   ax[3]);
            ax[0] = fmaf(u2f(w20.x).x, A2.y, ax[0]);
            ax[1] = fmaf(u2f(w20.y).x, A2.y, ax[1]);
            ax[2] = fmaf(u2f(w21.x).x, A2.y, ax[2]);
            ax[3] = fmaf(u2f(w21.y).x, A2.y, ax[3]);
        }
        // ReLU into register arrays (h1 never touches smem)
        float H1E[4][5], H1O[4][4];
        #pragma unroll
        for (int oc = 0; oc < 4; oc++) {
            #pragma unroll
            for (int m = 0; m < 4; m++) {
                float2 p = u2f(a1[m][oc]);
                H1E[oc][m] = fmaxf(p.x, 0.f);
                H1O[oc][m] = fmaxf(p.y, 0.f);
            }
            H1E[oc][4] = fmaxf(ax[oc], 0.f);
        }

        // ---- stage NEXT net's weights (LDG hidden under conv2/conv3; STS ordered
        //      before net dn+1's reads by the two barriers below) ----
        if (dn + 1 < NPG && tid < 204)
            ((float4*)(sm + WS_OFF + ((dn+1) & 1)*816))[tid] =
                __ldg((const float4*)(g_wdup + (size_t)(d+1)*408) + tid);

        // ======== conv2: K3 S2, 4->8ch; thread owns q = 4t..4t+3 (2 pairs) ========
        u64 a2[2][8];
        {
            ulonglong2 B0 = WQ[194], B1 = WQ[195], B2 = WQ[196], B3 = WQ[197];
            #pragma unroll
            for (int u = 0; u < 2; u++) {
                a2[u][0]=B0.x; a2[u][1]=B0.y; a2[u][2]=B1.x; a2[u][3]=B1.y;
                a2[u][4]=B2.x; a2[u][5]=B2.y; a2[u][6]=B3.x; a2[u][7]=B3.y;
            }
        }
        #pragma unroll
        for (int ch = 0; ch < 4; ch++) {
            const ulonglong2* wp = WQ + 48 + ch*12;
            ulonglong2 w0[4], w1[4], w2[4];
            #pragma unroll
            for (int j = 0; j < 4; j++) { w0[j]=wp[j]; w1[j]=wp[4+j]; w2[j]=wp[8+j]; }
            u64 PE0 = f2u(H1E[ch][0], H1E[ch][1]);
            u64 PE1 = f2u(H1E[ch][2], H1E[ch][3]);
            u64 PO0 = f2u(H1O[ch][0], H1O[ch][1]);
            u64 PO1 = f2u(H1O[ch][2], H1O[ch][3]);
            u64 X20 = f2u(H1E[ch][1], H1E[ch][2]);
            u64 X21 = f2u(H1E[ch][3], H1E[ch][4]);
            tap8(a2[0], PE0, w0);
            tap8(a2[0], PO0, w1);
            tap8(a2[0], X20, w2);
            tap8(a2[1], PE1, w0);
            tap8(a2[1], PO1, w1);
            tap8(a2[1], X21, w2);
        }
        // ReLU -> h2 pairs in registers
        u64 P20[8], P21[8];
        #pragma unroll
        for (int oc = 0; oc < 8; oc++) {
            float2 p0 = u2f(a2[0][oc]);
            float2 p1 = u2f(a2[1][oc]);
            P20[oc] = f2u(fmaxf(p0.x,0.f), fmaxf(p0.y,0.f));
            P21[oc] = f2u(fmaxf(p1.x,0.f), fmaxf(p1.y,0.f));
        }

        // ---- h2 halo: thread t needs (h2[4t+4], h2[4t+5]) = thread t+1's P20 ----
        if (lane == 0 && warp > 0) {
            #pragma unroll
            for (int oc = 0; oc < 8; oc++) hal[warp*8 + oc] = P20[oc];
        }
        __syncthreads();                                  // B1
        u64 PH[8];
        #pragma unroll
        for (int oc = 0; oc < 8; oc++) {
            PH[oc] = __shfl_down_sync(0xFFFFFFFFu, P20[oc], 1);
            if (lane == 31 && warp < 7) PH[oc] = hal[(warp+1)*8 + oc];
        }
        // t=255 PH is self-garbage: feeds only p>=1021, masked in the pool.

        // ======== conv3: K3 S1, 8->8ch, ReLU + pool; thread owns p = 4t..4t+3 ========
        float psum[8];
        #pragma unroll
        for (int i = 0; i < 8; i++) psum[i] = 0.f;
        {
            u64 a3[2][8];
            {
                ulonglong2 B0 = WQ[198], B1 = WQ[199], B2 = WQ[200], B3 = WQ[201];
                #pragma unroll
                for (int v = 0; v < 2; v++) {
                    a3[v][0]=B0.x; a3[v][1]=B0.y; a3[v][2]=B1.x; a3[v][3]=B1.y;
                    a3[v][4]=B2.x; a3[v][5]=B2.y; a3[v][6]=B3.x; a3[v][7]=B3.y;
                }
            }
            #pragma unroll 2
            for (int ch = 0; ch < 8; ch++) {
                const ulonglong2* wp = WQ + 96 + ch*12;
                ulonglong2 w0[4], w1[4], w2[4];
                #pragma unroll
                for (int j = 0; j < 4; j++) { w0[j]=wp[j]; w1[j]=wp[4+j]; w2[j]=wp[8+j]; }
                float2 q0 = u2f(P20[ch]);
                float2 q1 = u2f(P21[ch]);
                float2 qh = u2f(PH[ch]);
                u64 M1 = f2u(q0.y, q1.x);
                u64 M2 = f2u(q1.y, qh.x);
                tap8(a3[0], P20[ch], w0);
                tap8(a3[0], M1,       w1);
                tap8(a3[0], P21[ch], w2);
                tap8(a3[1], P21[ch], w0);
                tap8(a3[1], M2,       w1);
                tap8(a3[1], PH[ch],  w2);
            }
            const int p = 4*tid;
            const bool v0 = (p     < 1021), v1 = (p + 1 < 1021);
            const bool v2 = (p + 2 < 1021), v3 = (p + 3 < 1021);
            #pragma unroll
            for (int oc = 0; oc < 8; oc++) {
                float2 r0 = u2f(a3[0][oc]);
                float2 r1 = u2f(a3[1][oc]);
                psum[oc] += (v0 ? fmaxf(r0.x,0.f) : 0.f) + (v1 ? fmaxf(r0.y,0.f) : 0.f)
                          + (v2 ? fmaxf(r1.x,0.f) : 0.f) + (v3 ? fmaxf(r1.y,0.f) : 0.f);
            }
        }

        // ---- warp reduce psum -> red[warp][oc] ----
        #pragma unroll
        for (int oc = 0; oc < 8; oc++) {
            float s = psum[oc];
            #pragma unroll
            for (int off = 16; off > 0; off >>= 1)
                s += __shfl_down_sync(0xFFFFFFFFu, s, off);
            if (lane == 0) red[warp*8 + oc] = s;
        }
        __syncthreads();                                  // B2

        // ---- warp0: cross-warp reduce (8 warps) + head matvec ----
        if (warp == 0) {
            float s = red[lane] + red[lane + 32];
            s += __shfl_xor_sync(0xFFFFFFFFu, s, 8);
            s += __shfl_xor_sync(0xFFFFFFFFu, s, 16);
            float pj[8];
            #pragma unroll
            for (int j = 0; j < 8; j++)
                pj[j] = __shfl_sync(0xFFFFFFFFu, s, j);
            if (lane < CV) {
                float v = 0.f;
                #pragma unroll
                for (int j = 0; j < 8; j++)
                    v = fmaf(pj[j], cWh[(d*CV + lane)*8 + j], v);
                oacc = fmaf(v, cZ[d] * (1.0f/1021.0f), oacc);
            }
        }
        // hal/red hazards: next writes occur after B1/B2 of the next net,
        // which all threads (incl. warp0 readers) must pass first.
    }

    if (warp == 0 && lane < CV)
        atomicAdd(&out[b*CV + lane], oacc);
}

extern "C" void kernel_launch(void* const* d_in, const int* in_sizes, int n_in,
                              void* d_out, int out_size) {
    const int*   ids  = (const int*)  d_in[0];
    const float* mask = (const float*)d_in[1];
    const float* z    = (const float*)d_in[2];
    const float* emb  = (const float*)d_in[3];
    const float* W1   = (const float*)d_in[4];
    const float* b1   = (const float*)d_in[5];
    const float* W2   = (const float*)d_in[6];
    const float* b2   = (const float*)d_in[7];
    const float* W3   = (const float*)d_in[8];
    const float* b3   = (const float*)d_in[9];
    const float* Wh   = (const float*)d_in[10];
    const float* bh   = (const float*)d_in[11];
    float* out = (float*)d_out;

    cudaMemcpyToSymbolAsync(cWh, Wh, DZV*80*sizeof(float), 0, cudaMemcpyDeviceToDevice, 0);
    cudaMemcpyToSymbolAsync(cZ,  z,  DZV*sizeof(float),    0, cudaMemcpyDeviceToDevice, 0);

    prep_kernel<<<(DZV*404 + 255)/256, 256>>>(W1, b1, W2, b2, W3, b3, z, bh, out);

    cudaFuncSetAttribute(ensemble_kernel,
                         cudaFuncAttributeMaxDynamicSharedMemorySize,
                         SMEM_FLOATS * (int)sizeof(float));
    ensemble_kernel<<<dim3(B_TOT, 2), NT, SMEM_FLOATS * (int)sizeof(float)>>>(ids, mask, emb, out);
}

// round 11
// speedup vs baseline: 1.1043x; 1.1043x over previous
#include <cuda_runtime.h>

#define NT 256
#define L_IN 4096
#define DZV 30
#define CV 10
#define NPG 15
#define B_TOT 512

typedef unsigned long long u64;

__constant__ float cWh[DZV*80];   // [d][c][j]
__constant__ float cZ[DZV];

// per-net block of 408 u64, all weights pre-duplicated (w,w):
// [0..96)    conv1: ch*12 + k*4 + oc      (ch<8, k<3, oc<4)
// [96..192)  conv2: 96 + ch*24 + k*8 + oc (ch<4, k<3, oc<8)
// [192..384) conv3: 192 + ch*24 + k*8 + oc (ch<8)
// [384..388) b1d, [388..396) b2d, [396..404) b3d, pad 408
__device__ u64 g_wdup[DZV*408];

__device__ __forceinline__ u64 f2u(float a, float b) {
    union { float2 f; u64 u; } c; c.f = make_float2(a, b); return c.u;
}
__device__ __forceinline__ float2 u2f(u64 v) {
    union { float2 f; u64 u; } c; c.u = v; return c.f;
}
__device__ __forceinline__ u64 ffma2(u64 a, u64 b, u64 c) {
    u64 d; asm("fma.rn.f32x2 %0, %1, %2, %3;" : "=l"(d) : "l"(a), "l"(b), "l"(c)); return d;
}
__device__ __forceinline__ void tap4(u64* acc, u64 t, ulonglong2 wa, ulonglong2 wb) {
    acc[0] = ffma2(wa.x, t, acc[0]);
    acc[1] = ffma2(wa.y, t, acc[1]);
    acc[2] = ffma2(wb.x, t, acc[2]);
    acc[3] = ffma2(wb.y, t, acc[3]);
}
__device__ __forceinline__ void tap8(u64* acc, u64 t, const ulonglong2* w4) {
    acc[0] = ffma2(w4[0].x, t, acc[0]);
    acc[1] = ffma2(w4[0].y, t, acc[1]);
    acc[2] = ffma2(w4[1].x, t, acc[2]);
    acc[3] = ffma2(w4[1].y, t, acc[3]);
    acc[4] = ffma2(w4[2].x, t, acc[4]);
    acc[5] = ffma2(w4[2].y, t, acc[5]);
    acc[6] = ffma2(w4[3].x, t, acc[6]);
    acc[7] = ffma2(w4[3].y, t, acc[7]);
}

__global__ void prep_kernel(const float* __restrict__ W1, const float* __restrict__ b1,
                            const float* __restrict__ W2, const float* __restrict__ b2,
                            const float* __restrict__ W3, const float* __restrict__ b3,
                            const float* __restrict__ z,  const float* __restrict__ bh,
                            float* __restrict__ out) {
    int i = blockIdx.x * blockDim.x + threadIdx.x;
    if (i < DZV*404) {
        int n = i / 404, r = i % 404;
        float v;
        if (r < 96) {
            int ch = r / 12, k = (r % 12) / 4, oc = r & 3;
            v = W1[n*96 + oc*24 + ch*3 + k];
        } else if (r < 192) {
            int t = r - 96, ch = t / 24, k = (t % 24) / 8, oc = t & 7;
            v = W2[n*96 + oc*12 + ch*3 + k];
        } else if (r < 384) {
            int t = r - 192, ch = t / 24, k = (t % 24) / 8, oc = t & 7;
            v = W3[n*192 + oc*24 + ch*3 + k];
        } else if (r < 388) v = b1[n*4 + (r-384)];
        else if (r < 396)   v = b2[n*8 + (r-388)];
        else                v = b3[n*8 + (r-396)];
        g_wdup[n*408 + r] = f2u(v, v);
    }
    if (i < B_TOT*CV) {
        int c = i % CV;
        float s = 0.f;
        #pragma unroll
        for (int d = 0; d < DZV; d++) s = fmaf(z[d], bh[d*CV + c], s);
        out[i] = s;
    }
}

// ---- smem float offsets ----
// XS[ch][c][idx]: x[pos] at ch*CH_STR + (pos&7)*C_STR + (pos>>3)
#define C_STR  516          // ≡4 mod 32 -> conflict-free gather STS
#define CH_STR (8*C_STR)    // 4128
#define XS_SZ  (8*CH_STR)   // 33024
#define RED_OFF  33024      // [8 warps][8]
#define HAL1_OFF 33088      // 8 warps x 4 floats
#define HAL2_OFF 33120      // 8 warps x 16 floats
#define WS_OFF   33248      // 2 x 816 floats (16B aligned: 33248*4 % 16 == 0)
#define SMEM_FLOATS 34880   // 139520 B

__global__ __launch_bounds__(NT, 1)
void ensemble_kernel(const int* __restrict__ ids,
                     const float* __restrict__ mask,
                     const float* __restrict__ embed,
                     float* __restrict__ out)
{
    extern __shared__ float sm[];
    float* red  = sm + RED_OFF;
    float* hal1 = sm + HAL1_OFF;
    float* hal2 = sm + HAL2_OFF;

    const int tid  = threadIdx.x;
    const int lane = tid & 31;
    const int warp = tid >> 5;
    const int b    = blockIdx.x;
    const int g    = blockIdx.y;

    // ---- zero pads XS[ch][c][512..515] (256 slots, one per thread) ----
    {
        int ch = tid >> 5, c = (tid >> 2) & 7, j = tid & 3;
        sm[ch*CH_STR + c*C_STR + 512 + j] = 0.f;
    }

    // ---- stage first net's weight block into buffer 0 ----
    if (tid < 204)
        ((float4*)(sm + WS_OFF))[tid] =
            __ldg((const float4*)(g_wdup + (size_t)(g*NPG)*408) + tid);

    // ---- gather masked embeddings, mod-8 deinterleaved, channel-major ----
    #pragma unroll 1
    for (int i = tid; i < L_IN; i += NT) {
        int   id = __ldg(&ids[b*L_IN + i]);
        float m  = __ldg(&mask[b*L_IN + i]);
        float4 e0 = __ldg((const float4*)(embed + (size_t)id*8));
        float4 e1 = __ldg((const float4*)(embed + (size_t)id*8 + 4));
        float* bp = sm + (i & 7)*C_STR + (i >> 3);
        bp[0*CH_STR] = e0.x*m; bp[1*CH_STR] = e0.y*m;
        bp[2*CH_STR] = e0.z*m; bp[3*CH_STR] = e0.w*m;
        bp[4*CH_STR] = e1.x*m; bp[5*CH_STR] = e1.y*m;
        bp[6*CH_STR] = e1.z*m; bp[7*CH_STR] = e1.w*m;
    }
    __syncthreads();

    float oacc = 0.f;   // warp0, lane<CV

    #pragma unroll 1
    for (int dn = 0; dn < NPG; dn++) {
        const int d = g*NPG + dn;
        const ulonglong2* WQ = (const ulonglong2*)(sm + WS_OFF + (dn & 1)*816);

        // ======== conv1: K3 S2, 8->4ch. thread owns r = 8t..8t+7 as
        //          pairs PJ[oc][j] = (h1[8t+j], h1[8t+4+j]), j<4 ========
        u64 A1[4][4];   // [j][oc]
        {
            ulonglong2 B0 = WQ[192], B1 = WQ[193];
            #pragma unroll
            for (int j = 0; j < 4; j++) {
                A1[j][0] = B0.x; A1[j][1] = B0.y;
                A1[j][2] = B1.x; A1[j][3] = B1.y;
            }
        }
        #pragma unroll 2
        for (int ch = 0; ch < 8; ch++) {
            const float* Xc = sm + ch*CH_STR + 2*tid;
            // stride-8 x pairs P[m] = (x[16t+m], x[16t+8+m]), m=0..8
            u64 P[9];
            #pragma unroll
            for (int m = 0; m < 8; m++)
                P[m] = *(const u64*)(Xc + m*C_STR);
            {
                float2 e8 = *(const float2*)(Xc + 2);   // XS[ch][0][2t+2..3]
                P[8] = f2u(u2f(P[0]).y, e8.x);
            }
            ulonglong2 w00 = WQ[ch*6+0], w01 = WQ[ch*6+1];
            ulonglong2 w10 = WQ[ch*6+2], w11 = WQ[ch*6+3];
            ulonglong2 w20 = WQ[ch*6+4], w21 = WQ[ch*6+5];
            #pragma unroll
            for (int j = 0; j < 4; j++) {
                tap4(A1[j], P[2*j+0], w00, w01);
                tap4(A1[j], P[2*j+1], w10, w11);
                tap4(A1[j], P[2*j+2], w20, w21);
            }
        }
        // ReLU -> PJ[ch(=conv1 oc)][j]: stride-4 h1 pairs, register-resident
        u64 PJ[4][4];
        #pragma unroll
        for (int oc = 0; oc < 4; oc++)
            #pragma unroll
            for (int j = 0; j < 4; j++) {
                float2 p = u2f(A1[j][oc]);
                PJ[oc][j] = f2u(fmaxf(p.x, 0.f), fmaxf(p.y, 0.f));
            }

        // halo post: lane0 posts h1[8t] (lo of PJ[ch][0]) for left neighbor
        if (lane == 0) {
            #pragma unroll
            for (int ch = 0; ch < 4; ch++)
                hal1[warp*4 + ch] = u2f(PJ[ch][0]).x;
        }
        // stage NEXT net's weights (hidden under conv2/conv3)
        if (dn + 1 < NPG && tid < 204)
            ((float4*)(sm + WS_OFF + ((dn+1) & 1)*816))[tid] =
                __ldg((const float4*)(g_wdup + (size_t)(d+1)*408) + tid);
        __syncthreads();                                  // B1

        float hxlo[4];
        #pragma unroll
        for (int ch = 0; ch < 4; ch++)
            hxlo[ch] = __shfl_down_sync(0xFFFFFFFFu, u2f(PJ[ch][0]).x, 1);
        if (lane == 31 && warp < 7) {
            #pragma unroll
            for (int ch = 0; ch < 4; ch++)
                hxlo[ch] = hal1[(warp+1)*4 + ch];
        }
        // t=255: hxlo garbage -> feeds only dead q=1023 (masked downstream)

        // ======== conv2: K3 S2, 4->8ch. q = 4t..4t+3 as
        //          pairs QI[oc][i] = (h2[4t+i], h2[4t+2+i]), i<2 ========
        u64 A2[2][8];
        {
            ulonglong2 B0 = WQ[194], B1 = WQ[195], B2 = WQ[196], B3 = WQ[197];
            #pragma unroll
            for (int i = 0; i < 2; i++) {
                A2[i][0]=B0.x; A2[i][1]=B0.y; A2[i][2]=B1.x; A2[i][3]=B1.y;
                A2[i][4]=B2.x; A2[i][5]=B2.y; A2[i][6]=B3.x; A2[i][7]=B3.y;
            }
        }
        #pragma unroll
        for (int ch = 0; ch < 4; ch++) {
            const ulonglong2* wp = WQ + 48 + ch*12;
            ulonglong2 w0[4], w1[4], w2[4];
            #pragma unroll
            for (int j = 0; j < 4; j++) { w0[j]=wp[j]; w1[j]=wp[4+j]; w2[j]=wp[8+j]; }
            u64 HX = f2u(u2f(PJ[ch][0]).y, hxlo[ch]);   // h1 pair @ 8t+4
            tap8(A2[0], PJ[ch][0], w0);
            tap8(A2[0], PJ[ch][1], w1);
            tap8(A2[0], PJ[ch][2], w2);
            tap8(A2[1], PJ[ch][2], w0);
            tap8(A2[1], PJ[ch][3], w1);
            tap8(A2[1], HX,        w2);
        }
        // ReLU -> QI[oc][i]: stride-2 h2 pairs
        u64 QI[8][2];
        #pragma unroll
        for (int oc = 0; oc < 8; oc++)
            #pragma unroll
            for (int i = 0; i < 2; i++) {
                float2 p = u2f(A2[i][oc]);
                QI[oc][i] = f2u(fmaxf(p.x, 0.f), fmaxf(p.y, 0.f));
            }

        // halo post: lane0 posts h2[4t], h2[4t+1] (lo of each pair)
        if (lane == 0) {
            #pragma unroll
            for (int ch = 0; ch < 8; ch++) {
                hal2[warp*16 + ch]     = u2f(QI[ch][0]).x;
                hal2[warp*16 + 8 + ch] = u2f(QI[ch][1]).x;
            }
        }
        __syncthreads();                                  // B2

        float h2lo0[8], h2lo1[8];
        #pragma unroll
        for (int ch = 0; ch < 8; ch++) {
            h2lo0[ch] = __shfl_down_sync(0xFFFFFFFFu, u2f(QI[ch][0]).x, 1);
            h2lo1[ch] = __shfl_down_sync(0xFFFFFFFFu, u2f(QI[ch][1]).x, 1);
        }
        if (lane == 31 && warp < 7) {
            #pragma unroll
            for (int ch = 0; ch < 8; ch++) {
                h2lo0[ch] = hal2[(warp+1)*16 + ch];
                h2lo1[ch] = hal2[(warp+1)*16 + 8 + ch];
            }
        }

        // ======== conv3: K3 S1, 8->8ch, ReLU + pool.
        //          pairs (4t, 4t+2) and (4t+1, 4t+3); valid p < 1021 ========
        float psum[8];
        #pragma unroll
        for (int i = 0; i < 8; i++) psum[i] = 0.f;
        {
            u64 A3[2][8];
            {
                ulonglong2 B0 = WQ[198], B1 = WQ[199], B2 = WQ[200], B3 = WQ[201];
                #pragma unroll
                for (int i = 0; i < 2; i++) {
                    A3[i][0]=B0.x; A3[i][1]=B0.y; A3[i][2]=B1.x; A3[i][3]=B1.y;
                    A3[i][4]=B2.x; A3[i][5]=B2.y; A3[i][6]=B3.x; A3[i][7]=B3.y;
                }
            }
            #pragma unroll 2
            for (int ch = 0; ch < 8; ch++) {
                const ulonglong2* wp = WQ + 96 + ch*12;
                ulonglong2 w0[4], w1[4], w2[4];
                #pragma unroll
                for (int j = 0; j < 4; j++) { w0[j]=wp[j]; w1[j]=wp[4+j]; w2[j]=wp[8+j]; }
                u64 H0 = f2u(u2f(QI[ch][0]).y, h2lo0[ch]);  // pair @ 4t+2
                u64 H1 = f2u(u2f(QI[ch][1]).y, h2lo1[ch]);  // pair @ 4t+3
                tap8(A3[0], QI[ch][0], w0);
                tap8(A3[0], QI[ch][1], w1);
                tap8(A3[0], H0,        w2);
                tap8(A3[1], QI[ch][1], w0);
                tap8(A3[1], H0,        w1);
                tap8(A3[1], H1,        w2);
            }
            const int p = 4*tid;
            const bool v0 = (p     < 1021);   // lo A3[0]
            const bool v2 = (p + 2 < 1021);   // hi A3[0]
            const bool v1 = (p + 1 < 1021);   // lo A3[1]
            const bool v3 = (p + 3 < 1021);   // hi A3[1]
            #pragma unroll
            for (int oc = 0; oc < 8; oc++) {
                float2 r0 = u2f(A3[0][oc]);
                float2 r1 = u2f(A3[1][oc]);
                psum[oc] += (v0 ? fmaxf(r0.x,0.f) : 0.f) + (v2 ? fmaxf(r0.y,0.f) : 0.f)
                          + (v1 ? fmaxf(r1.x,0.f) : 0.f) + (v3 ? fmaxf(r1.y,0.f) : 0.f);
            }
        }

        // ---- warp reduce psum -> red[warp][oc] ----
        #pragma unroll
        for (int oc = 0; oc < 8; oc++) {
            float s = psum[oc];
            #pragma unroll
            for (int off = 16; off > 0; off >>= 1)
                s += __shfl_down_sync(0xFFFFFFFFu, s, off);
            if (lane == 0) red[warp*8 + oc] = s;
        }
        __syncthreads();                                  // B3

        // ---- warp0: cross-warp reduce (8 warps) + head matvec ----
        if (warp == 0) {
            float s = red[lane] + red[lane + 32];
            s += __shfl_xor_sync(0xFFFFFFFFu, s, 8);
            s += __shfl_xor_sync(0xFFFFFFFFu, s, 16);
            float pj[8];
            #pragma unroll
            for (int j = 0; j < 8; j++)
                pj[j] = __shfl_sync(0xFFFFFFFFu, s, j);
            if (lane < CV) {
                float v = 0.f;
                #pragma unroll
                for (int j = 0; j < 8; j++)
                    v = fmaf(pj[j], cWh[(d*CV + lane)*8 + j], v);
                oacc = fmaf(v, cZ[d] * (1.0f/1021.0f), oacc);
            }
        }
        // hal1/hal2/red hazards: each rewritten only after a barrier (B1/B2/B3
        // of the next net) that all readers have already passed.
    }

    if (warp == 0 && lane < CV)
        atomicAdd(&out[b*CV + lane], oacc);
}

extern "C" void kernel_launch(void* const* d_in, const int* in_sizes, int n_in,
                              void* d_out, int out_size) {
    const int*   ids  = (const int*)  d_in[0];
    const float* mask = (const float*)d_in[1];
    const float* z    = (const float*)d_in[2];
    const float* emb  = (const float*)d_in[3];
    const float* W1   = (const float*)d_in[4];
    const float* b1   = (const float*)d_in[5];
    const float* W2   = (const float*)d_in[6];
    const float* b2   = (const float*)d_in[7];
    const float* W3   = (const float*)d_in[8];
    const float* b3   = (const float*)d_in[9];
    const float* Wh   = (const float*)d_in[10];
    const float* bh   = (const float*)d_in[11];
    float* out = (float*)d_out;

    cudaMemcpyToSymbolAsync(cWh, Wh, DZV*80*sizeof(float), 0, cudaMemcpyDeviceToDevice, 0);
    cudaMemcpyToSymbolAsync(cZ,  z,  DZV*sizeof(float),    0, cudaMemcpyDeviceToDevice, 0);

    prep_kernel<<<(DZV*404 + 255)/256, 256>>>(W1, b1, W2, b2, W3, b3, z, bh, out);

    cudaFuncSetAttribute(ensemble_kernel,
                         cudaFuncAttributeMaxDynamicSharedMemorySize,
                         SMEM_FLOATS * (int)sizeof(float));
    ensemble_kernel<<<dim3(B_TOT, 2), NT, SMEM_FLOATS * (int)sizeof(float)>>>(ids, mask, emb, out);
}

// round 12
// speedup vs baseline: 1.2633x; 1.1439x over previous
#include <cuda_runtime.h>
#include <cuda_fp16.h>

#define NT 256
#define L_IN 4096
#define DZV 30
#define CV 10
#define NPG 15
#define B_TOT 512

typedef unsigned long long u64;

__constant__ float cWh[DZV*80];   // [d][c][j]
__constant__ float cZ[DZV];

// per-net block of 408 u64, all weights pre-duplicated (w,w):
// [0..96)    conv1: ch*12 + k*4 + oc      (ch<8, k<3, oc<4)
// [96..192)  conv2: 96 + ch*24 + k*8 + oc (ch<4, k<3, oc<8)
// [192..384) conv3: 192 + ch*24 + k*8 + oc (ch<8)
// [384..388) b1d, [388..396) b2d, [396..404) b3d, pad 408
__device__ u64 g_wdup[DZV*408];

__device__ __forceinline__ u64 f2u(float a, float b) {
    union { float2 f; u64 u; } c; c.f = make_float2(a, b); return c.u;
}
__device__ __forceinline__ float2 u2f(u64 v) {
    union { float2 f; u64 u; } c; c.u = v; return c.f;
}
__device__ __forceinline__ u64 ffma2(u64 a, u64 b, u64 c) {
    u64 d; asm("fma.rn.f32x2 %0, %1, %2, %3;" : "=l"(d) : "l"(a), "l"(b), "l"(c)); return d;
}
__device__ __forceinline__ void tap4(u64* acc, u64 t, ulonglong2 wa, ulonglong2 wb) {
    acc[0] = ffma2(wa.x, t, acc[0]);
    acc[1] = ffma2(wa.y, t, acc[1]);
    acc[2] = ffma2(wb.x, t, acc[2]);
    acc[3] = ffma2(wb.y, t, acc[3]);
}
__device__ __forceinline__ void tap8(u64* acc, u64 t, const ulonglong2* w4) {
    acc[0] = ffma2(w4[0].x, t, acc[0]);
    acc[1] = ffma2(w4[0].y, t, acc[1]);
    acc[2] = ffma2(w4[1].x, t, acc[2]);
    acc[3] = ffma2(w4[1].y, t, acc[3]);
    acc[4] = ffma2(w4[2].x, t, acc[4]);
    acc[5] = ffma2(w4[2].y, t, acc[5]);
    acc[6] = ffma2(w4[3].x, t, acc[6]);
    acc[7] = ffma2(w4[3].y, t, acc[7]);
}

__global__ void prep_kernel(const float* __restrict__ W1, const float* __restrict__ b1,
                            const float* __restrict__ W2, const float* __restrict__ b2,
                            const float* __restrict__ W3, const float* __restrict__ b3,
                            const float* __restrict__ z,  const float* __restrict__ bh,
                            float* __restrict__ out) {
    int i = blockIdx.x * blockDim.x + threadIdx.x;
    if (i < DZV*404) {
        int n = i / 404, r = i % 404;
        float v;
        if (r < 96) {
            int ch = r / 12, k = (r % 12) / 4, oc = r & 3;
            v = W1[n*96 + oc*24 + ch*3 + k];
        } else if (r < 192) {
            int t = r - 96, ch = t / 24, k = (t % 24) / 8, oc = t & 7;
            v = W2[n*96 + oc*12 + ch*3 + k];
        } else if (r < 384) {
            int t = r - 192, ch = t / 24, k = (t % 24) / 8, oc = t & 7;
            v = W3[n*192 + oc*24 + ch*3 + k];
        } else if (r < 388) v = b1[n*4 + (r-384)];
        else if (r < 396)   v = b2[n*8 + (r-388)];
        else                v = b3[n*8 + (r-396)];
        g_wdup[n*408 + r] = f2u(v, v);
    }
    if (i < B_TOT*CV) {
        int c = i % CV;
        float s = 0.f;
        #pragma unroll
        for (int d = 0; d < DZV; d++) s = fmaf(z[d], bh[d*CV + c], s);
        out[i] = s;
    }
}

// ---- smem layout ----
// XS (fp16): x[pos] at half index ch*CH_STR + (pos&7)*C_STR + (pos>>3)
#define C_STR   516          // halfs; 516B*2... byte stride 1032 ≡ 8 mod 128
#define CH_STR  (8*C_STR)    // 4128 halfs
#define XS_F32  16512        // 8*CH_STR halfs = 16512 float-slots
#define RED_OFF  16512       // [8 warps][8]
#define HAL1_OFF 16576       // 8 warps x 4
#define HAL2_OFF 16608       // 8 warps x 16
#define WS_OFF   16736       // 2 x 816 floats (16B aligned: 16736*4 % 16 == 0)
#define SMEM_FLOATS 18368    // 73472 B  -> 2 CTAs/SM

__global__ __launch_bounds__(NT, 2)
void ensemble_kernel(const int* __restrict__ ids,
                     const float* __restrict__ mask,
                     const float* __restrict__ embed,
                     float* __restrict__ out)
{
    extern __shared__ float sm[];
    __half* smh = (__half*)sm;
    float* red  = sm + RED_OFF;
    float* hal1 = sm + HAL1_OFF;
    float* hal2 = sm + HAL2_OFF;

    const int tid  = threadIdx.x;
    const int lane = tid & 31;
    const int warp = tid >> 5;
    const int b    = blockIdx.x;
    const int g    = blockIdx.y;

    // ---- zero pads XS[ch][c][512..515] (256 slots, one per thread) ----
    {
        int ch = tid >> 5, c = (tid >> 2) & 7, j = tid & 3;
        smh[ch*CH_STR + c*C_STR + 512 + j] = __float2half_rn(0.f);
    }

    // ---- stage first net's weight block into buffer 0 ----
    if (tid < 204)
        ((float4*)(sm + WS_OFF))[tid] =
            __ldg((const float4*)(g_wdup + (size_t)(g*NPG)*408) + tid);

    // ---- gather masked embeddings -> fp16, mod-8 deinterleaved ----
    #pragma unroll 1
    for (int i = tid; i < L_IN; i += NT) {
        int   id = __ldg(&ids[b*L_IN + i]);
        float m  = __ldg(&mask[b*L_IN + i]);
        float4 e0 = __ldg((const float4*)(embed + (size_t)id*8));
        float4 e1 = __ldg((const float4*)(embed + (size_t)id*8 + 4));
        __half* bp = smh + (i & 7)*C_STR + (i >> 3);
        bp[0*CH_STR] = __float2half_rn(e0.x*m);
        bp[1*CH_STR] = __float2half_rn(e0.y*m);
        bp[2*CH_STR] = __float2half_rn(e0.z*m);
        bp[3*CH_STR] = __float2half_rn(e0.w*m);
        bp[4*CH_STR] = __float2half_rn(e1.x*m);
        bp[5*CH_STR] = __float2half_rn(e1.y*m);
        bp[6*CH_STR] = __float2half_rn(e1.z*m);
        bp[7*CH_STR] = __float2half_rn(e1.w*m);
    }
    __syncthreads();

    float oacc = 0.f;   // warp0, lane<CV

    #pragma unroll 1
    for (int dn = 0; dn < NPG; dn++) {
        const int d = g*NPG + dn;
        const ulonglong2* WQ = (const ulonglong2*)(sm + WS_OFF + (dn & 1)*816);

        // ======== conv1: K3 S2, 8->4ch. thread owns r = 8t..8t+7 as
        //          pairs PJ[oc][j] = (h1[8t+j], h1[8t+4+j]), j<4 ========
        u64 A1[4][4];   // [j][oc]
        {
            ulonglong2 B0 = WQ[192], B1 = WQ[193];
            #pragma unroll
            for (int j = 0; j < 4; j++) {
                A1[j][0] = B0.x; A1[j][1] = B0.y;
                A1[j][2] = B1.x; A1[j][3] = B1.y;
            }
        }
        #pragma unroll 2
        for (int ch = 0; ch < 8; ch++) {
            // stride-8 x pairs as half2: P[m] = (x[16t+m], x[16t+8+m]), m<8
            const __half2* Xc = ((const __half2*)smh) + ch*(CH_STR/2) + tid;
            float2 F[8];
            #pragma unroll
            for (int m = 0; m < 8; m++)
                F[m] = __half22float2(Xc[m*(C_STR/2)]);
            float2 Fe = __half22float2(Xc[1]);   // (x[16t+16], x[16t+24])
            u64 P[9];
            #pragma unroll
            for (int m = 0; m < 8; m++) P[m] = f2u(F[m].x, F[m].y);
            P[8] = f2u(F[0].y, Fe.x);            // (x[16t+8], x[16t+16])
            ulonglong2 w00 = WQ[ch*6+0], w01 = WQ[ch*6+1];
            ulonglong2 w10 = WQ[ch*6+2], w11 = WQ[ch*6+3];
            ulonglong2 w20 = WQ[ch*6+4], w21 = WQ[ch*6+5];
            #pragma unroll
            for (int j = 0; j < 4; j++) {
                tap4(A1[j], P[2*j+0], w00, w01);
                tap4(A1[j], P[2*j+1], w10, w11);
                tap4(A1[j], P[2*j+2], w20, w21);
            }
        }
        // ReLU -> PJ[ch(=conv1 oc)][j]: stride-4 h1 pairs, register-resident
        u64 PJ[4][4];
        #pragma unroll
        for (int oc = 0; oc < 4; oc++)
            #pragma unroll
            for (int j = 0; j < 4; j++) {
                float2 p = u2f(A1[j][oc]);
                PJ[oc][j] = f2u(fmaxf(p.x, 0.f), fmaxf(p.y, 0.f));
            }

        // halo post: lane0 posts h1[8t] (lo of PJ[ch][0]) for left neighbor
        if (lane == 0) {
            #pragma unroll
            for (int ch = 0; ch < 4; ch++)
                hal1[warp*4 + ch] = u2f(PJ[ch][0]).x;
        }
        // stage NEXT net's weights (hidden under conv2/conv3)
        if (dn + 1 < NPG && tid < 204)
            ((float4*)(sm + WS_OFF + ((dn+1) & 1)*816))[tid] =
                __ldg((const float4*)(g_wdup + (size_t)(d+1)*408) + tid);
        __syncthreads();                                  // B1

        float hxlo[4];
        #pragma unroll
        for (int ch = 0; ch < 4; ch++)
            hxlo[ch] = __shfl_down_sync(0xFFFFFFFFu, u2f(PJ[ch][0]).x, 1);
        if (lane == 31 && warp < 7) {
            #pragma unroll
            for (int ch = 0; ch < 4; ch++)
                hxlo[ch] = hal1[(warp+1)*4 + ch];
        }
        // t=255: hxlo garbage -> feeds only dead q=1023 (masked downstream)

        // ======== conv2: K3 S2, 4->8ch. q = 4t..4t+3 as
        //          pairs QI[oc][i] = (h2[4t+i], h2[4t+2+i]), i<2 ========
        u64 A2[2][8];
        {
            ulonglong2 B0 = WQ[194], B1 = WQ[195], B2 = WQ[196], B3 = WQ[197];
            #pragma unroll
            for (int i = 0; i < 2; i++) {
                A2[i][0]=B0.x; A2[i][1]=B0.y; A2[i][2]=B1.x; A2[i][3]=B1.y;
                A2[i][4]=B2.x; A2[i][5]=B2.y; A2[i][6]=B3.x; A2[i][7]=B3.y;
            }
        }
        #pragma unroll
        for (int ch = 0; ch < 4; ch++) {
            const ulonglong2* wp = WQ + 48 + ch*12;
            ulonglong2 w0[4], w1[4], w2[4];
            #pragma unroll
            for (int j = 0; j < 4; j++) { w0[j]=wp[j]; w1[j]=wp[4+j]; w2[j]=wp[8+j]; }
            u64 HX = f2u(u2f(PJ[ch][0]).y, hxlo[ch]);   // h1 pair @ 8t+4
            tap8(A2[0], PJ[ch][0], w0);
            tap8(A2[0], PJ[ch][1], w1);
            tap8(A2[0], PJ[ch][2], w2);
            tap8(A2[1], PJ[ch][2], w0);
            tap8(A2[1], PJ[ch][3], w1);
            tap8(A2[1], HX,        w2);
        }
        // ReLU -> QI[oc][i]: stride-2 h2 pairs
        u64 QI[8][2];
        #pragma unroll
        for (int oc = 0; oc < 8; oc++)
            #pragma unroll
            for (int i = 0; i < 2; i++) {
                float2 p = u2f(A2[i][oc]);
                QI[oc][i] = f2u(fmaxf(p.x, 0.f), fmaxf(p.y, 0.f));
            }

        // halo post: lane0 posts h2[4t], h2[4t+1] (lo of each pair)
        if (lane == 0) {
            #pragma unroll
            for (int ch = 0; ch < 8; ch++) {
                hal2[warp*16 + ch]     = u2f(QI[ch][0]).x;
                hal2[warp*16 + 8 + ch] = u2f(QI[ch][1]).x;
            }
        }
        __syncthreads();                                  // B2

        float h2lo0[8], h2lo1[8];
        #pragma unroll
        for (int ch = 0; ch < 8; ch++) {
            h2lo0[ch] = __shfl_down_sync(0xFFFFFFFFu, u2f(QI[ch][0]).x, 1);
            h2lo1[ch] = __shfl_down_sync(0xFFFFFFFFu, u2f(QI[ch][1]).x, 1);
        }
        if (lane == 31 && warp < 7) {
            #pragma unroll
            for (int ch = 0; ch < 8; ch++) {
                h2lo0[ch] = hal2[(warp+1)*16 + ch];
                h2lo1[ch] = hal2[(warp+1)*16 + 8 + ch];
            }
        }

        // ======== conv3: K3 S1, 8->8ch, ReLU + pool.
        //          pairs (4t, 4t+2) and (4t+1, 4t+3); valid p < 1021 ========
        float psum[8];
        #pragma unroll
        for (int i = 0; i < 8; i++) psum[i] = 0.f;
        {
            u64 A3[2][8];
            {
                ulonglong2 B0 = WQ[198], B1 = WQ[199], B2 = WQ[200], B3 = WQ[201];
                #pragma unroll
                for (int i = 0; i < 2; i++) {
                    A3[i][0]=B0.x; A3[i][1]=B0.y; A3[i][2]=B1.x; A3[i][3]=B1.y;
                    A3[i][4]=B2.x; A3[i][5]=B2.y; A3[i][6]=B3.x; A3[i][7]=B3.y;
                }
            }
            #pragma unroll 2
            for (int ch = 0; ch < 8; ch++) {
                const ulonglong2* wp = WQ + 96 + ch*12;
                ulonglong2 w0[4], w1[4], w2[4];
                #pragma unroll
                for (int j = 0; j < 4; j++) { w0[j]=wp[j]; w1[j]=wp[4+j]; w2[j]=wp[8+j]; }
                u64 H0 = f2u(u2f(QI[ch][0]).y, h2lo0[ch]);  // pair @ 4t+2
                u64 H1 = f2u(u2f(QI[ch][1]).y, h2lo1[ch]);  // pair @ 4t+3
                tap8(A3[0], QI[ch][0], w0);
                tap8(A3[0], QI[ch][1], w1);
                tap8(A3[0], H0,        w2);
                tap8(A3[1], QI[ch][1], w0);
                tap8(A3[1], H0,        w1);
                tap8(A3[1], H1,        w2);
            }
            const int p = 4*tid;
            const bool v0 = (p     < 1021);
            const bool v2 = (p + 2 < 1021);
            const bool v1 = (p + 1 < 1021);
            const bool v3 = (p + 3 < 1021);
            #pragma unroll
            for (int oc = 0; oc < 8; oc++) {
                float2 r0 = u2f(A3[0][oc]);
                float2 r1 = u2f(A3[1][oc]);
                psum[oc] += (v0 ? fmaxf(r0.x,0.f) : 0.f) + (v2 ? fmaxf(r0.y,0.f) : 0.f)
                          + (v1 ? fmaxf(r1.x,0.f) : 0.f) + (v3 ? fmaxf(r1.y,0.f) : 0.f);
            }
        }

        // ---- warp reduce psum -> red[warp][oc] ----
        #pragma unroll
        for (int oc = 0; oc < 8; oc++) {
            float s = psum[oc];
            #pragma unroll
            for (int off = 16; off > 0; off >>= 1)
                s += __shfl_down_sync(0xFFFFFFFFu, s, off);
            if (lane == 0) red[warp*8 + oc] = s;
        }
        __syncthreads();                                  // B3

        // ---- warp0: cross-warp reduce (8 warps) + head matvec ----
        if (warp == 0) {
            float s = red[lane] + red[lane + 32];
            s += __shfl_xor_sync(0xFFFFFFFFu, s, 8);
            s += __shfl_xor_sync(0xFFFFFFFFu, s, 16);
            float pj[8];
            #pragma unroll
            for (int j = 0; j < 8; j++)
                pj[j] = __shfl_sync(0xFFFFFFFFu, s, j);
            if (lane < CV) {
                float v = 0.f;
                #pragma unroll
                for (int j = 0; j < 8; j++)
                    v = fmaf(pj[j], cWh[(d*CV + lane)*8 + j], v);
                oacc = fmaf(v, cZ[d] * (1.0f/1021.0f), oacc);
            }
        }
        // hal1/hal2/red hazards: each rewritten only after a barrier (B1/B2/B3
        // of the next net) that all readers have already passed.
    }

    if (warp == 0 && lane < CV)
        atomicAdd(&out[b*CV + lane], oacc);
}

extern "C" void kernel_launch(void* const* d_in, const int* in_sizes, int n_in,
                              void* d_out, int out_size) {
    const int*   ids  = (const int*)  d_in[0];
    const float* mask = (const float*)d_in[1];
    const float* z    = (const float*)d_in[2];
    const float* emb  = (const float*)d_in[3];
    const float* W1   = (const float*)d_in[4];
    const float* b1   = (const float*)d_in[5];
    const float* W2   = (const float*)d_in[6];
    const float* b2   = (const float*)d_in[7];
    const float* W3   = (const float*)d_in[8];
    const float* b3   = (const float*)d_in[9];
    const float* Wh   = (const float*)d_in[10];
    const float* bh   = (const float*)d_in[11];
    float* out = (float*)d_out;

    cudaMemcpyToSymbolAsync(cWh, Wh, DZV*80*sizeof(float), 0, cudaMemcpyDeviceToDevice, 0);
    cudaMemcpyToSymbolAsync(cZ,  z,  DZV*sizeof(float),    0, cudaMemcpyDeviceToDevice, 0);

    prep_kernel<<<(DZV*404 + 255)/256, 256>>>(W1, b1, W2, b2, W3, b3, z, bh, out);

    cudaFuncSetAttribute(ensemble_kernel,
                         cudaFuncAttributeMaxDynamicSharedMemorySize,
                         SMEM_FLOATS * (int)sizeof(float));
    ensemble_kernel<<<dim3(B_TOT, 2), NT, SMEM_FLOATS * (int)sizeof(float)>>>(ids, mask, emb, out);
}

// round 13
// speedup vs baseline: 1.2739x; 1.0084x over previous
#include <cuda_runtime.h>
#include <cuda_fp16.h>

#define NT 256
#define L_IN 4096
#define DZV 30
#define CV 10
#define B_TOT 512

typedef unsigned long long u64;

__constant__ float cWh[DZV*80];   // [d][c][j]
__constant__ float cZ[DZV];

// per-net block of 408 u64, all weights pre-duplicated (w,w):
// [0..96)    conv1: ch*12 + k*4 + oc      (ch<8, k<3, oc<4)
// [96..192)  conv2: 96 + ch*24 + k*8 + oc (ch<4, k<3, oc<8)
// [192..384) conv3: 192 + ch*24 + k*8 + oc (ch<8)
// [384..388) b1d, [388..396) b2d, [396..404) b3d, pad 408
__device__ u64 g_wdup[DZV*408];

__device__ __forceinline__ u64 f2u(float a, float b) {
    union { float2 f; u64 u; } c; c.f = make_float2(a, b); return c.u;
}
__device__ __forceinline__ float2 u2f(u64 v) {
    union { float2 f; u64 u; } c; c.u = v; return c.f;
}
__device__ __forceinline__ u64 ffma2(u64 a, u64 b, u64 c) {
    u64 d; asm("fma.rn.f32x2 %0, %1, %2, %3;" : "=l"(d) : "l"(a), "l"(b), "l"(c)); return d;
}
__device__ __forceinline__ void tap4(u64* acc, u64 t, ulonglong2 wa, ulonglong2 wb) {
    acc[0] = ffma2(wa.x, t, acc[0]);
    acc[1] = ffma2(wa.y, t, acc[1]);
    acc[2] = ffma2(wb.x, t, acc[2]);
    acc[3] = ffma2(wb.y, t, acc[3]);
}
__device__ __forceinline__ void tap8(u64* acc, u64 t, const ulonglong2* w4) {
    acc[0] = ffma2(w4[0].x, t, acc[0]);
    acc[1] = ffma2(w4[0].y, t, acc[1]);
    acc[2] = ffma2(w4[1].x, t, acc[2]);
    acc[3] = ffma2(w4[1].y, t, acc[3]);
    acc[4] = ffma2(w4[2].x, t, acc[4]);
    acc[5] = ffma2(w4[2].y, t, acc[5]);
    acc[6] = ffma2(w4[3].x, t, acc[6]);
    acc[7] = ffma2(w4[3].y, t, acc[7]);
}

__global__ void prep_kernel(const float* __restrict__ W1, const float* __restrict__ b1,
                            const float* __restrict__ W2, const float* __restrict__ b2,
                            const float* __restrict__ W3, const float* __restrict__ b3,
                            const float* __restrict__ z,  const float* __restrict__ bh,
                            float* __restrict__ out) {
    int i = blockIdx.x * blockDim.x + threadIdx.x;
    if (i < DZV*404) {
        int n = i / 404, r = i % 404;
        float v;
        if (r < 96) {
            int ch = r / 12, k = (r % 12) / 4, oc = r & 3;
            v = W1[n*96 + oc*24 + ch*3 + k];
        } else if (r < 192) {
            int t = r - 96, ch = t / 24, k = (t % 24) / 8, oc = t & 7;
            v = W2[n*96 + oc*12 + ch*3 + k];
        } else if (r < 384) {
            int t = r - 192, ch = t / 24, k = (t % 24) / 8, oc = t & 7;
            v = W3[n*192 + oc*24 + ch*3 + k];
        } else if (r < 388) v = b1[n*4 + (r-384)];
        else if (r < 396)   v = b2[n*8 + (r-388)];
        else                v = b3[n*8 + (r-396)];
        g_wdup[n*408 + r] = f2u(v, v);
    }
    if (i < B_TOT*CV) {
        int c = i % CV;
        float s = 0.f;
        #pragma unroll
        for (int d = 0; d < DZV; d++) s = fmaf(z[d], bh[d*CV + c], s);
        out[i] = s;
    }
}

// ---- smem layout ----
// XS (fp16): x[pos] at half index ch*CH_STR + (pos&7)*C_STR + (pos>>3)
#define C_STR    516
#define CH_STR   (8*C_STR)    // 4128 halfs
#define RED_OFF  16512        // 16 nets x 64 floats
#define HAL1_OFF 17536        // 8 warps x 8
#define HAL2_OFF 17600        // 2 parities x 8 warps x 16
#define WS_OFF   17856        // 4 x 816 floats (pair ping-pong); 17856*4 % 16 == 0
#define SMEM_FLOATS 21120     // 84480 B -> 2 CTAs/SM

__global__ __launch_bounds__(NT, 2)
void ensemble_kernel(const int* __restrict__ ids,
                     const float* __restrict__ mask,
                     const float* __restrict__ embed,
                     float* __restrict__ out)
{
    extern __shared__ float sm[];
    __half* smh = (__half*)sm;
    float* red  = sm + RED_OFF;
    float* hal1 = sm + HAL1_OFF;
    float* hal2 = sm + HAL2_OFF;

    const int tid  = threadIdx.x;
    const int lane = tid & 31;
    const int warp = tid >> 5;
    const int b    = blockIdx.x;
    const int g    = blockIdx.y;
    const int base_net = g * 16;      // g0: nets 0..15 (8 pairs), g1: 16..29 (7 pairs)
    const int np       = 8 - g;

    // ---- zero pads XS[ch][c][512..515] (one slot per thread) ----
    {
        int ch = tid >> 5, c = (tid >> 2) & 7, j = tid & 3;
        smh[ch*CH_STR + c*C_STR + 512 + j] = __float2half_rn(0.f);
    }

    // ---- stage pair 0 (two nets = 408 float4) into buffers 0,1 ----
    for (int j = tid; j < 408; j += NT)
        ((float4*)(sm + WS_OFF))[j] =
            __ldg((const float4*)g_wdup + (size_t)base_net*204 + j);

    // ---- gather masked embeddings -> fp16, mod-8 deinterleaved ----
    #pragma unroll 1
    for (int i = tid; i < L_IN; i += NT) {
        int   id = __ldg(&ids[b*L_IN + i]);
        float m  = __ldg(&mask[b*L_IN + i]);
        float4 e0 = __ldg((const float4*)(embed + (size_t)id*8));
        float4 e1 = __ldg((const float4*)(embed + (size_t)id*8 + 4));
        __half* bp = smh + (i & 7)*C_STR + (i >> 3);
        bp[0*CH_STR] = __float2half_rn(e0.x*m);
        bp[1*CH_STR] = __float2half_rn(e0.y*m);
        bp[2*CH_STR] = __float2half_rn(e0.z*m);
        bp[3*CH_STR] = __float2half_rn(e0.w*m);
        bp[4*CH_STR] = __float2half_rn(e1.x*m);
        bp[5*CH_STR] = __float2half_rn(e1.y*m);
        bp[6*CH_STR] = __float2half_rn(e1.z*m);
        bp[7*CH_STR] = __float2half_rn(e1.w*m);
    }
    __syncthreads();

    float oacc = 0.f;

    #pragma unroll 1
    for (int p = 0; p < np; p++) {
        const ulonglong2* WQA = (const ulonglong2*)(sm + WS_OFF + ((p & 1)*2)*816);
        const ulonglong2* WQB = WQA + 204;
        const ulonglong2* WQn[2] = {WQA, WQB};

        // ======== conv1 (PAIRED): K3 S2, 8->4ch; x loaded ONCE for 2 nets ========
        u64 A1[2][4][4];   // [net][j][oc]
        #pragma unroll
        for (int n = 0; n < 2; n++) {
            ulonglong2 Ba = WQn[n][192], Bb = WQn[n][193];
            #pragma unroll
            for (int j = 0; j < 4; j++) {
                A1[n][j][0] = Ba.x; A1[n][j][1] = Ba.y;
                A1[n][j][2] = Bb.x; A1[n][j][3] = Bb.y;
            }
        }
        #pragma unroll 2
        for (int ch = 0; ch < 8; ch++) {
            const __half2* Xc = ((const __half2*)smh) + ch*(CH_STR/2) + tid;
            float2 F[8];
            #pragma unroll
            for (int m = 0; m < 8; m++) F[m] = __half22float2(Xc[m*(C_STR/2)]);
            float2 Fe = __half22float2(Xc[1]);
            u64 P[9];
            #pragma unroll
            for (int m = 0; m < 8; m++) P[m] = f2u(F[m].x, F[m].y);
            P[8] = f2u(F[0].y, Fe.x);
            #pragma unroll
            for (int n = 0; n < 2; n++) {
                ulonglong2 w00 = WQn[n][ch*6+0], w01 = WQn[n][ch*6+1];
                ulonglong2 w10 = WQn[n][ch*6+2], w11 = WQn[n][ch*6+3];
                ulonglong2 w20 = WQn[n][ch*6+4], w21 = WQn[n][ch*6+5];
                #pragma unroll
                for (int j = 0; j < 4; j++) {
                    tap4(A1[n][j], P[2*j+0], w00, w01);
                    tap4(A1[n][j], P[2*j+1], w10, w11);
                    tap4(A1[n][j], P[2*j+2], w20, w21);
                }
            }
        }
        // ReLU -> PJ[net][ch][j] = (h1[8t+j], h1[8t+4+j]) pairs, register-resident
        u64 PJ[2][4][4];
        #pragma unroll
        for (int n = 0; n < 2; n++)
            #pragma unroll
            for (int oc = 0; oc < 4; oc++)
                #pragma unroll
                for (int j = 0; j < 4; j++) {
                    float2 q = u2f(A1[n][j][oc]);
                    PJ[n][oc][j] = f2u(fmaxf(q.x, 0.f), fmaxf(q.y, 0.f));
                }

        // halo post for both nets
        if (lane == 0) {
            #pragma unroll
            for (int n = 0; n < 2; n++)
                #pragma unroll
                for (int ch = 0; ch < 4; ch++)
                    hal1[warp*8 + n*4 + ch] = u2f(PJ[n][ch][0]).x;
        }
        __syncthreads();                                  // B1 (shared by pair)

        // prefetch NEXT pair's weights (dst = pair p-1 buffers; their last reads
        // were in pair p-1 conv3, fully ordered before this point by B1 above)
        if (p + 1 < np) {
            float4* dst = (float4*)(sm + WS_OFF + (((p+1) & 1)*2)*816);
            const float4* src = (const float4*)g_wdup + (size_t)(base_net + 2*(p+1))*204;
            for (int j = tid; j < 408; j += NT) dst[j] = __ldg(src + j);
        }

        float hx[2][4];
        #pragma unroll
        for (int n = 0; n < 2; n++)
            #pragma unroll
            for (int ch = 0; ch < 4; ch++)
                hx[n][ch] = __shfl_down_sync(0xFFFFFFFFu, u2f(PJ[n][ch][0]).x, 1);
        if (lane == 31 && warp < 7) {
            #pragma unroll
            for (int n = 0; n < 2; n++)
                #pragma unroll
                for (int ch = 0; ch < 4; ch++)
                    hx[n][ch] = hal1[(warp+1)*8 + n*4 + ch];
        }
        // t=255: hx garbage -> feeds only dead q=1023 (masked downstream)

        // ======== per net: conv2 -> conv3 -> pool -> store partial ========
        #pragma unroll
        for (int n = 0; n < 2; n++) {
            const ulonglong2* WQ = WQn[n];

            // ---- conv2: K3 S2, 4->8ch ----
            u64 A2[2][8];
            {
                ulonglong2 B0 = WQ[194], B1 = WQ[195], B2 = WQ[196], B3 = WQ[197];
                #pragma unroll
                for (int i = 0; i < 2; i++) {
                    A2[i][0]=B0.x; A2[i][1]=B0.y; A2[i][2]=B1.x; A2[i][3]=B1.y;
                    A2[i][4]=B2.x; A2[i][5]=B2.y; A2[i][6]=B3.x; A2[i][7]=B3.y;
                }
            }
            #pragma unroll
            for (int ch = 0; ch < 4; ch++) {
                const ulonglong2* wp = WQ + 48 + ch*12;
                ulonglong2 w0[4], w1[4], w2[4];
                #pragma unroll
                for (int j = 0; j < 4; j++) { w0[j]=wp[j]; w1[j]=wp[4+j]; w2[j]=wp[8+j]; }
                u64 HX = f2u(u2f(PJ[n][ch][0]).y, hx[n][ch]);   // h1 pair @ 8t+4
                tap8(A2[0], PJ[n][ch][0], w0);
                tap8(A2[0], PJ[n][ch][1], w1);
                tap8(A2[0], PJ[n][ch][2], w2);
                tap8(A2[1], PJ[n][ch][2], w0);
                tap8(A2[1], PJ[n][ch][3], w1);
                tap8(A2[1], HX,           w2);
            }
            u64 QI[8][2];
            #pragma unroll
            for (int oc = 0; oc < 8; oc++)
                #pragma unroll
                for (int i = 0; i < 2; i++) {
                    float2 q = u2f(A2[i][oc]);
                    QI[oc][i] = f2u(fmaxf(q.x, 0.f), fmaxf(q.y, 0.f));
                }

            // h2 halo, per-net-parity buffer (race-free without a third barrier)
            float* h2b = hal2 + n*128;
            if (lane == 0) {
                #pragma unroll
                for (int ch = 0; ch < 8; ch++) {
                    h2b[warp*16 + ch]     = u2f(QI[ch][0]).x;
                    h2b[warp*16 + 8 + ch] = u2f(QI[ch][1]).x;
                }
            }
            __syncthreads();                              // B2_n
            float l0[8], l1[8];
            #pragma unroll
            for (int ch = 0; ch < 8; ch++) {
                l0[ch] = __shfl_down_sync(0xFFFFFFFFu, u2f(QI[ch][0]).x, 1);
                l1[ch] = __shfl_down_sync(0xFFFFFFFFu, u2f(QI[ch][1]).x, 1);
            }
            if (lane == 31 && warp < 7) {
                #pragma unroll
                for (int ch = 0; ch < 8; ch++) {
                    l0[ch] = h2b[(warp+1)*16 + ch];
                    l1[ch] = h2b[(warp+1)*16 + 8 + ch];
                }
            }

            // ---- conv3: K3 S1, 8->8ch, ReLU + pool (oc-halved for regs) ----
            float ps[8];
            #pragma unroll
            for (int i = 0; i < 8; i++) ps[i] = 0.f;
            #pragma unroll
            for (int h = 0; h < 2; h++) {
                u64 A3[2][4];
                {
                    ulonglong2 Ba = WQ[198 + 2*h], Bb = WQ[199 + 2*h];
                    A3[0][0]=Ba.x; A3[0][1]=Ba.y; A3[0][2]=Bb.x; A3[0][3]=Bb.y;
                    A3[1][0]=Ba.x; A3[1][1]=Ba.y; A3[1][2]=Bb.x; A3[1][3]=Bb.y;
                }
                #pragma unroll 2
                for (int ch = 0; ch < 8; ch++) {
                    const ulonglong2* wp = WQ + 96 + ch*12 + 2*h;
                    ulonglong2 k0a = wp[0], k0b = wp[1];
                    ulonglong2 k1a = wp[4], k1b = wp[5];
                    ulonglong2 k2a = wp[8], k2b = wp[9];
                    u64 H0 = f2u(u2f(QI[ch][0]).y, l0[ch]);   // pair @ 4t+2
                    u64 H1 = f2u(u2f(QI[ch][1]).y, l1[ch]);   // pair @ 4t+3
                    tap4(A3[0], QI[ch][0], k0a, k0b);
                    tap4(A3[0], QI[ch][1], k1a, k1b);
                    tap4(A3[0], H0,        k2a, k2b);
                    tap4(A3[1], QI[ch][1], k0a, k0b);
                    tap4(A3[1], H0,        k1a, k1b);
                    tap4(A3[1], H1,        k2a, k2b);
                }
                const int pb = 4*tid;
                const bool v0 = (pb     < 1021), v2 = (pb + 2 < 1021);
                const bool v1 = (pb + 1 < 1021), v3 = (pb + 3 < 1021);
                #pragma unroll
                for (int o = 0; o < 4; o++) {
                    float2 r0 = u2f(A3[0][o]);
                    float2 r1 = u2f(A3[1][o]);
                    ps[4*h+o] += (v0 ? fmaxf(r0.x,0.f) : 0.f) + (v2 ? fmaxf(r0.y,0.f) : 0.f)
                               + (v1 ? fmaxf(r1.x,0.f) : 0.f) + (v3 ? fmaxf(r1.y,0.f) : 0.f);
                }
            }

            // ---- warp reduce -> red[net][warp][oc]; NO barrier, head deferred ----
            #pragma unroll
            for (int oc = 0; oc < 8; oc++) {
                float s = ps[oc];
                #pragma unroll
                for (int off = 16; off > 0; off >>= 1)
                    s += __shfl_down_sync(0xFFFFFFFFu, s, off);
                if (lane == 0) red[(2*p + n)*64 + warp*8 + oc] = s;
            }
        }
    }
    __syncthreads();   // final: all red slots visible

    // ---- deferred head, parallel across warps: warp w handles nets w, w+8 ----
    const int nets = 2*np;
    #pragma unroll 1
    for (int nn = warp; nn < nets; nn += 8) {
        const int d = base_net + nn;
        float s = red[nn*64 + lane] + red[nn*64 + 32 + lane];
        s += __shfl_xor_sync(0xFFFFFFFFu, s, 8);
        s += __shfl_xor_sync(0xFFFFFFFFu, s, 16);
        float pj[8];
        #pragma unroll
        for (int j = 0; j < 8; j++)
            pj[j] = __shfl_sync(0xFFFFFFFFu, s, j);
        if (lane < CV) {
            float v = 0.f;
            #pragma unroll
            for (int j = 0; j < 8; j++)
                v = fmaf(pj[j], cWh[(d*CV + lane)*8 + j], v);
            oacc = fmaf(v, cZ[d] * (1.0f/1021.0f), oacc);
        }
    }
    if (lane < CV)
        atomicAdd(&out[b*CV + lane], oacc);
}

extern "C" void kernel_launch(void* const* d_in, const int* in_sizes, int n_in,
                              void* d_out, int out_size) {
    const int*   ids  = (const int*)  d_in[0];
    const float* mask = (const float*)d_in[1];
    const float* z    = (const float*)d_in[2];
    const float* emb  = (const float*)d_in[3];
    const float* W1   = (const float*)d_in[4];
    const float* b1   = (const float*)d_in[5];
    const float* W2   = (const float*)d_in[6];
    const float* b2   = (const float*)d_in[7];
    const float* W3   = (const float*)d_in[8];
    const float* b3   = (const float*)d_in[9];
    const float* Wh   = (const float*)d_in[10];
    const float* bh   = (const float*)d_in[11];
    float* out = (float*)d_out;

    cudaMemcpyToSymbolAsync(cWh, Wh, DZV*80*sizeof(float), 0, cudaMemcpyDeviceToDevice, 0);
    cudaMemcpyToSymbolAsync(cZ,  z,  DZV*sizeof(float),    0, cudaMemcpyDeviceToDevice, 0);

    prep_kernel<<<(DZV*404 + 255)/256, 256>>>(W1, b1, W2, b2, W3, b3, z, bh, out);

    cudaFuncSetAttribute(ensemble_kernel,
                         cudaFuncAttributeMaxDynamicSharedMemorySize,
                         SMEM_FLOATS * (int)sizeof(float));
    ensemble_kernel<<<dim3(B_TOT, 2), NT, SMEM_FLOATS * (int)sizeof(float)>>>(ids, mask, emb, out);
}